// round 15
// baseline (speedup 1.0000x reference)
#include <cuda_runtime.h>

// ---------------------------------------------------------------------------
// Routing_2259152797848: capsule routing
// R15 = R13 (best: 258.1us) with ONE change:
//       k_route __launch_bounds__(256, 5) -> forces <=51 regs
//       -> 5 blocks/SM = 40 resident warps (was 4 blocks / 32 warps).
//       k_route body + k_fc byte-identical to R13.
// ---------------------------------------------------------------------------

#define MAXN 50016
#define D    128
#define CH   8
#define KD   16
#define M    32

__device__ float g_z[(size_t)(MAXN + 1) * D];
__device__ int   g_is64;

// --- FC + relu + per-capsule normalize: 64 rows, 256 threads (R13) -------------
__global__ void k_fc(const float* __restrict__ x, const float* __restrict__ W,
                     const float* __restrict__ b, const int* __restrict__ nidw,
                     int n) {
    extern __shared__ float smem[];
    float* w_s = smem;             // [128][132]
    float* x_s = smem + 128 * 132; // [64][128]

    const int t = threadIdx.x;
    const int r0 = blockIdx.x * 64;

    // folded init (block 0 only): zero pad row + id-width sniff
    if (blockIdx.x == 0) {
        if (t < 128) g_z[(size_t)n * D + t] = 0.0f;
        else if (t < 160) {
            int lane = t - 128;
            int any = 0;
            #pragma unroll
            for (int i = 0; i < 4; i++) any |= nidw[2 * (lane * 4 + i) + 1];
            unsigned msk = __ballot_sync(0xffffffffu, any != 0);
            if (lane == 0) g_is64 = (msk == 0) ? 1 : 0;
        }
    }

    // load W (4096 float4), padded rows of 33 float4
    const float4* W4 = (const float4*)W;
    float4* ws4 = (float4*)w_s;
    #pragma unroll
    for (int i = 0; i < 16; i++) {
        int idx4 = t + 256 * i;
        int j = idx4 >> 5, kk = idx4 & 31;
        ws4[j * 33 + kk] = W4[idx4];
    }
    // load x tile (2048 float4), zero-fill past n
    const float4* X4 = (const float4*)x;
    float4* xs4 = (float4*)x_s;
    #pragma unroll
    for (int i = 0; i < 8; i++) {
        int idx4 = t + 256 * i;
        int r = idx4 >> 5, kk = idx4 & 31;
        float4 v = make_float4(0.f, 0.f, 0.f, 0.f);
        if (r0 + r < n) v = X4[(size_t)(r0 + r) * 32 + kk];
        xs4[r * 32 + kk] = v;
    }
    __syncthreads();

    const int tx = t & 31;   // column lane
    const int ty = t >> 5;   // row group (0..7)

    float acc[8][4];
    #pragma unroll
    for (int rr = 0; rr < 8; rr++)
        #pragma unroll
        for (int cc = 0; cc < 4; cc++) acc[rr][cc] = 0.f;

    #pragma unroll 4
    for (int k4 = 0; k4 < 32; k4++) {
        float4 wv[4];
        #pragma unroll
        for (int cc = 0; cc < 4; cc++) wv[cc] = ws4[(tx + 32 * cc) * 33 + k4];
        float4 xr[8];
        #pragma unroll
        for (int rr = 0; rr < 8; rr++) xr[rr] = xs4[(ty + 8 * rr) * 32 + k4];
        #pragma unroll
        for (int rr = 0; rr < 8; rr++)
            #pragma unroll
            for (int cc = 0; cc < 4; cc++) {
                acc[rr][cc] = fmaf(xr[rr].x, wv[cc].x, acc[rr][cc]);
                acc[rr][cc] = fmaf(xr[rr].y, wv[cc].y, acc[rr][cc]);
                acc[rr][cc] = fmaf(xr[rr].z, wv[cc].z, acc[rr][cc]);
                acc[rr][cc] = fmaf(xr[rr].w, wv[cc].w, acc[rr][cc]);
            }
    }

    float bv[4];
    #pragma unroll
    for (int cc = 0; cc < 4; cc++) bv[cc] = b[tx + 32 * cc];

    // relu + bias + per-capsule (16-col) normalize (16-lane shfl groups)
    #pragma unroll
    for (int rr = 0; rr < 8; rr++) {
        int row = r0 + ty + 8 * rr;
        #pragma unroll
        for (int cc = 0; cc < 4; cc++) {
            float v = fmaxf(acc[rr][cc] + bv[cc], 0.f);
            float s = v * v;
            s += __shfl_xor_sync(0xffffffffu, s, 1);
            s += __shfl_xor_sync(0xffffffffu, s, 2);
            s += __shfl_xor_sync(0xffffffffu, s, 4);
            s += __shfl_xor_sync(0xffffffffu, s, 8);
            float inv = rsqrtf(fmaxf(s, 1e-24f));
            if (row < n) g_z[(size_t)row * D + tx + 32 * cc] = v * inv;
        }
    }
}

// --- routing: 256 threads = 2 independent nodes (body R4/R10 VERBATIM) ---------
// ONLY change: launch_bounds minBlocksPerMultiprocessor 4 -> 5 (regs 64 -> <=51).
__global__ void __launch_bounds__(256, 5)
k_route(const void* __restrict__ nid_raw, float* __restrict__ out, int n) {
    __shared__ float d_s[2][M * 9];          // d_s[grp][m*9+c]
    __shared__ __align__(16) float ps[2][CH * 36];  // ps[grp][c*36+m]
    __shared__ int ids[2][M];

    const int t   = threadIdx.x;
    const int grp = t >> 7;                  // node group 0/1
    const int tl  = t & 127;
    const int bid = 1 + grp;                 // named barrier id (warp-uniform)
    const int node = blockIdx.x * 2 + grp;
    if (node >= n) return;                   // whole 128-group exits together
    const int is64 = g_is64;

    if (tl < M) {
        long long id;
        if (is64) id = ((const long long*)nid_raw)[(size_t)node * M + tl];
        else      id = (long long)((const int*)nid_raw)[(size_t)node * M + tl];
        ids[grp][tl] = (int)id;
    }
    const float xc = g_z[(size_t)node * D + tl];
    asm volatile("bar.sync %0, %1;" :: "r"(bid), "r"(128) : "memory");

    // coalesced gather: one (c,k) column of all 32 neighbor rows
    float nbr[M];
    #pragma unroll
    for (int m = 0; m < M; m++)
        nbr[m] = g_z[(size_t)ids[grp][m] * D + tl];

    const int cB = tl >> 4;          // channel (tree / phase B)
    const int g  = tl & 15;          // lane within 16-lane channel group
    const int m0 = tl >> 3;          // softmax identity
    const int cA = tl & 7;
    const int mbase = ((g & 1) << 4) | ((g & 2) << 2) | (g & 4) | ((g >> 3) << 1);

    float u_val = xc;
    float acc;

    for (int it = 0; it < 3; it++) {
        // ---- tree: d[m] = sum_k u[c,k]*nb[m,c,k], split over 16 lanes ----
        float s1[16];
        #pragma unroll
        for (int i = 0; i < 16; i++) {
            float lo = u_val * nbr[i];
            float hi = u_val * nbr[i + 16];
            float keep = (g & 1) ? hi : lo;
            float send = (g & 1) ? lo : hi;
            s1[i] = keep + __shfl_xor_sync(0xffffffffu, send, 1);
        }
        float s2[8];
        #pragma unroll
        for (int i = 0; i < 8; i++) {
            float keep = (g & 2) ? s1[i + 8] : s1[i];
            float send = (g & 2) ? s1[i] : s1[i + 8];
            s2[i] = keep + __shfl_xor_sync(0xffffffffu, send, 2);
        }
        float s3[4];
        #pragma unroll
        for (int i = 0; i < 4; i++) {
            float keep = (g & 4) ? s2[i + 4] : s2[i];
            float send = (g & 4) ? s2[i] : s2[i + 4];
            s3[i] = keep + __shfl_xor_sync(0xffffffffu, send, 4);
        }
        float s4[2];
        #pragma unroll
        for (int i = 0; i < 2; i++) {
            float keep = (g & 8) ? s3[i + 2] : s3[i];
            float send = (g & 8) ? s3[i] : s3[i + 2];
            s4[i] = keep + __shfl_xor_sync(0xffffffffu, send, 8);
        }
        // |d| <= 1 (unit capsules): exp safe without max-subtraction
        d_s[grp][(mbase + 0) * 9 + cB] = __expf(s4[0]);
        d_s[grp][(mbase + 1) * 9 + cB] = __expf(s4[1]);
        asm volatile("bar.sync %0, %1;" :: "r"(bid), "r"(128) : "memory");

        // ---- softmax over c (8 adjacent lanes), thread = (m0, cA) ----
        float e0 = d_s[grp][m0 * 9 + cA];
        float e1 = d_s[grp][(m0 + 16) * 9 + cA];
        float sm0 = e0, sm1 = e1;
        sm0 += __shfl_xor_sync(0xffffffffu, sm0, 1);
        sm1 += __shfl_xor_sync(0xffffffffu, sm1, 1);
        sm0 += __shfl_xor_sync(0xffffffffu, sm0, 2);
        sm1 += __shfl_xor_sync(0xffffffffu, sm1, 2);
        sm0 += __shfl_xor_sync(0xffffffffu, sm0, 4);
        sm1 += __shfl_xor_sync(0xffffffffu, sm1, 4);
        ps[grp][cA * 36 + m0]      = __fdividef(e0, sm0);
        ps[grp][cA * 36 + m0 + 16] = __fdividef(e1, sm1);
        asm volatile("bar.sync %0, %1;" :: "r"(bid), "r"(128) : "memory");

        // ---- phase B: u[c,k] = x_caps + sum_m p[m,c]*nb[m,c,k] ----
        acc = xc;
        #pragma unroll
        for (int j = 0; j < 8; j++) {
            float4 p = *(const float4*)&ps[grp][cB * 36 + 4 * j];
            acc = fmaf(p.x, nbr[4 * j + 0], acc);
            acc = fmaf(p.y, nbr[4 * j + 1], acc);
            acc = fmaf(p.z, nbr[4 * j + 2], acc);
            acc = fmaf(p.w, nbr[4 * j + 3], acc);
        }

        if (it < 2) {
            float sq = acc * acc;
            sq += __shfl_xor_sync(0xffffffffu, sq, 1);
            sq += __shfl_xor_sync(0xffffffffu, sq, 2);
            sq += __shfl_xor_sync(0xffffffffu, sq, 4);
            sq += __shfl_xor_sync(0xffffffffu, sq, 8);
            u_val = acc * rsqrtf(fmaxf(sq, 1e-24f));
        } else {
            out[(size_t)node * D + tl] = acc;
        }
    }
}

// ---------------------------------------------------------------------------
extern "C" void kernel_launch(void* const* d_in, const int* in_sizes, int n_in,
                              void* d_out, int out_size) {
    const float* x = (const float*)d_in[0];
    const float* W = (const float*)d_in[1];
    const float* b = (const float*)d_in[2];
    const void*  nid = d_in[3];
    float* out = (float*)d_out;

    int n = in_sizes[0] / D;

    // W smem [128][132] + x smem [64][128] = 100,352 bytes
    static const size_t FC_SMEM = (size_t)(128 * 132 + 64 * 128) * sizeof(float);
    cudaFuncSetAttribute(k_fc, cudaFuncAttributeMaxDynamicSharedMemorySize,
                         (int)FC_SMEM);

    int nblk = (n + 63) / 64;
    k_fc<<<nblk, 256, FC_SMEM>>>(x, W, b, (const int*)nid, n);
    k_route<<<(n + 1) / 2, 256>>>(nid, out, n);
}

// round 16
// speedup vs baseline: 1.1136x; 1.1136x over previous
#include <cuda_runtime.h>

// ---------------------------------------------------------------------------
// Routing_2259152797848: capsule routing — FINAL (R13 configuration, 258.1us)
//   k_fc   : 64 rows / 256 threads (16 warps/SM), FFMA-floor-bound (~44us)
//   k_route: 2 nodes / 256 threads, single coalesced register gather +
//            SEL shuffle-tree + 8-lane softmax (issue-bound floor, ~210us)
//   init   : folded into k_fc block 0 (pad-row zero + id-width sniff)
// ---------------------------------------------------------------------------

#define MAXN 50016
#define D    128
#define CH   8
#define KD   16
#define M    32

__device__ float g_z[(size_t)(MAXN + 1) * D];
__device__ int   g_is64;

// --- FC + relu + per-capsule normalize: 64 rows, 256 threads -------------------
__global__ void k_fc(const float* __restrict__ x, const float* __restrict__ W,
                     const float* __restrict__ b, const int* __restrict__ nidw,
                     int n) {
    extern __shared__ float smem[];
    float* w_s = smem;             // [128][132]
    float* x_s = smem + 128 * 132; // [64][128]

    const int t = threadIdx.x;
    const int r0 = blockIdx.x * 64;

    // folded init (block 0 only): zero pad row + id-width sniff
    // (int64 ids in [0,n] have all odd 32-bit words zero)
    if (blockIdx.x == 0) {
        if (t < 128) g_z[(size_t)n * D + t] = 0.0f;
        else if (t < 160) {
            int lane = t - 128;
            int any = 0;
            #pragma unroll
            for (int i = 0; i < 4; i++) any |= nidw[2 * (lane * 4 + i) + 1];
            unsigned msk = __ballot_sync(0xffffffffu, any != 0);
            if (lane == 0) g_is64 = (msk == 0) ? 1 : 0;
        }
    }

    // load W (4096 float4), padded rows of 33 float4
    const float4* W4 = (const float4*)W;
    float4* ws4 = (float4*)w_s;
    #pragma unroll
    for (int i = 0; i < 16; i++) {
        int idx4 = t + 256 * i;
        int j = idx4 >> 5, kk = idx4 & 31;
        ws4[j * 33 + kk] = W4[idx4];
    }
    // load x tile (2048 float4), zero-fill past n
    const float4* X4 = (const float4*)x;
    float4* xs4 = (float4*)x_s;
    #pragma unroll
    for (int i = 0; i < 8; i++) {
        int idx4 = t + 256 * i;
        int r = idx4 >> 5, kk = idx4 & 31;
        float4 v = make_float4(0.f, 0.f, 0.f, 0.f);
        if (r0 + r < n) v = X4[(size_t)(r0 + r) * 32 + kk];
        xs4[r * 32 + kk] = v;
    }
    __syncthreads();

    const int tx = t & 31;   // column lane
    const int ty = t >> 5;   // row group (0..7)

    float acc[8][4];
    #pragma unroll
    for (int rr = 0; rr < 8; rr++)
        #pragma unroll
        for (int cc = 0; cc < 4; cc++) acc[rr][cc] = 0.f;

    #pragma unroll 4
    for (int k4 = 0; k4 < 32; k4++) {
        float4 wv[4];
        #pragma unroll
        for (int cc = 0; cc < 4; cc++) wv[cc] = ws4[(tx + 32 * cc) * 33 + k4];
        float4 xr[8];
        #pragma unroll
        for (int rr = 0; rr < 8; rr++) xr[rr] = xs4[(ty + 8 * rr) * 32 + k4];
        #pragma unroll
        for (int rr = 0; rr < 8; rr++)
            #pragma unroll
            for (int cc = 0; cc < 4; cc++) {
                acc[rr][cc] = fmaf(xr[rr].x, wv[cc].x, acc[rr][cc]);
                acc[rr][cc] = fmaf(xr[rr].y, wv[cc].y, acc[rr][cc]);
                acc[rr][cc] = fmaf(xr[rr].z, wv[cc].z, acc[rr][cc]);
                acc[rr][cc] = fmaf(xr[rr].w, wv[cc].w, acc[rr][cc]);
            }
    }

    float bv[4];
    #pragma unroll
    for (int cc = 0; cc < 4; cc++) bv[cc] = b[tx + 32 * cc];

    // relu + bias + per-capsule (16-col) normalize (16-lane shfl groups)
    #pragma unroll
    for (int rr = 0; rr < 8; rr++) {
        int row = r0 + ty + 8 * rr;
        #pragma unroll
        for (int cc = 0; cc < 4; cc++) {
            float v = fmaxf(acc[rr][cc] + bv[cc], 0.f);
            float s = v * v;
            s += __shfl_xor_sync(0xffffffffu, s, 1);
            s += __shfl_xor_sync(0xffffffffu, s, 2);
            s += __shfl_xor_sync(0xffffffffu, s, 4);
            s += __shfl_xor_sync(0xffffffffu, s, 8);
            float inv = rsqrtf(fmaxf(s, 1e-24f));
            if (row < n) g_z[(size_t)row * D + tx + 32 * cc] = v * inv;
        }
    }
}

// --- routing: 256 threads = 2 independent nodes --------------------------------
__global__ __launch_bounds__(256) void k_route(const void* __restrict__ nid_raw,
                                               float* __restrict__ out, int n) {
    __shared__ float d_s[2][M * 9];          // d_s[grp][m*9+c]
    __shared__ __align__(16) float ps[2][CH * 36];  // ps[grp][c*36+m]
    __shared__ int ids[2][M];

    const int t   = threadIdx.x;
    const int grp = t >> 7;                  // node group 0/1
    const int tl  = t & 127;
    const int bid = 1 + grp;                 // named barrier id (warp-uniform)
    const int node = blockIdx.x * 2 + grp;
    if (node >= n) return;                   // whole 128-group exits together
    const int is64 = g_is64;

    if (tl < M) {
        long long id;
        if (is64) id = ((const long long*)nid_raw)[(size_t)node * M + tl];
        else      id = (long long)((const int*)nid_raw)[(size_t)node * M + tl];
        ids[grp][tl] = (int)id;
    }
    const float xc = g_z[(size_t)node * D + tl];
    asm volatile("bar.sync %0, %1;" :: "r"(bid), "r"(128) : "memory");

    // coalesced gather: one (c,k) column of all 32 neighbor rows
    float nbr[M];
    #pragma unroll
    for (int m = 0; m < M; m++)
        nbr[m] = g_z[(size_t)ids[grp][m] * D + tl];

    const int cB = tl >> 4;          // channel (tree / phase B)
    const int g  = tl & 15;          // lane within 16-lane channel group
    const int m0 = tl >> 3;          // softmax identity
    const int cA = tl & 7;
    const int mbase = ((g & 1) << 4) | ((g & 2) << 2) | (g & 4) | ((g >> 3) << 1);

    float u_val = xc;
    float acc;

    for (int it = 0; it < 3; it++) {
        // ---- tree: d[m] = sum_k u[c,k]*nb[m,c,k], split over 16 lanes ----
        float s1[16];
        #pragma unroll
        for (int i = 0; i < 16; i++) {
            float lo = u_val * nbr[i];
            float hi = u_val * nbr[i + 16];
            float keep = (g & 1) ? hi : lo;
            float send = (g & 1) ? lo : hi;
            s1[i] = keep + __shfl_xor_sync(0xffffffffu, send, 1);
        }
        float s2[8];
        #pragma unroll
        for (int i = 0; i < 8; i++) {
            float keep = (g & 2) ? s1[i + 8] : s1[i];
            float send = (g & 2) ? s1[i] : s1[i + 8];
            s2[i] = keep + __shfl_xor_sync(0xffffffffu, send, 2);
        }
        float s3[4];
        #pragma unroll
        for (int i = 0; i < 4; i++) {
            float keep = (g & 4) ? s2[i + 4] : s2[i];
            float send = (g & 4) ? s2[i] : s2[i + 4];
            s3[i] = keep + __shfl_xor_sync(0xffffffffu, send, 4);
        }
        float s4[2];
        #pragma unroll
        for (int i = 0; i < 2; i++) {
            float keep = (g & 8) ? s3[i + 2] : s3[i];
            float send = (g & 8) ? s3[i] : s3[i + 2];
            s4[i] = keep + __shfl_xor_sync(0xffffffffu, send, 8);
        }
        // |d| <= 1 (unit capsules): exp safe without max-subtraction
        d_s[grp][(mbase + 0) * 9 + cB] = __expf(s4[0]);
        d_s[grp][(mbase + 1) * 9 + cB] = __expf(s4[1]);
        asm volatile("bar.sync %0, %1;" :: "r"(bid), "r"(128) : "memory");

        // ---- softmax over c (8 adjacent lanes), thread = (m0, cA) ----
        float e0 = d_s[grp][m0 * 9 + cA];
        float e1 = d_s[grp][(m0 + 16) * 9 + cA];
        float sm0 = e0, sm1 = e1;
        sm0 += __shfl_xor_sync(0xffffffffu, sm0, 1);
        sm1 += __shfl_xor_sync(0xffffffffu, sm1, 1);
        sm0 += __shfl_xor_sync(0xffffffffu, sm0, 2);
        sm1 += __shfl_xor_sync(0xffffffffu, sm1, 2);
        sm0 += __shfl_xor_sync(0xffffffffu, sm0, 4);
        sm1 += __shfl_xor_sync(0xffffffffu, sm1, 4);
        ps[grp][cA * 36 + m0]      = __fdividef(e0, sm0);
        ps[grp][cA * 36 + m0 + 16] = __fdividef(e1, sm1);
        asm volatile("bar.sync %0, %1;" :: "r"(bid), "r"(128) : "memory");

        // ---- phase B: u[c,k] = x_caps + sum_m p[m,c]*nb[m,c,k] ----
        acc = xc;
        #pragma unroll
        for (int j = 0; j < 8; j++) {
            float4 p = *(const float4*)&ps[grp][cB * 36 + 4 * j];
            acc = fmaf(p.x, nbr[4 * j + 0], acc);
            acc = fmaf(p.y, nbr[4 * j + 1], acc);
            acc = fmaf(p.z, nbr[4 * j + 2], acc);
            acc = fmaf(p.w, nbr[4 * j + 3], acc);
        }

        if (it < 2) {
            float sq = acc * acc;
            sq += __shfl_xor_sync(0xffffffffu, sq, 1);
            sq += __shfl_xor_sync(0xffffffffu, sq, 2);
            sq += __shfl_xor_sync(0xffffffffu, sq, 4);
            sq += __shfl_xor_sync(0xffffffffu, sq, 8);
            u_val = acc * rsqrtf(fmaxf(sq, 1e-24f));
        } else {
            out[(size_t)node * D + tl] = acc;
        }
    }
}

// ---------------------------------------------------------------------------
extern "C" void kernel_launch(void* const* d_in, const int* in_sizes, int n_in,
                              void* d_out, int out_size) {
    const float* x = (const float*)d_in[0];
    const float* W = (const float*)d_in[1];
    const float* b = (const float*)d_in[2];
    const void*  nid = d_in[3];
    float* out = (float*)d_out;

    int n = in_sizes[0] / D;

    // W smem [128][132] + x smem [64][128] = 100,352 bytes
    static const size_t FC_SMEM = (size_t)(128 * 132 + 64 * 128) * sizeof(float);
    cudaFuncSetAttribute(k_fc, cudaFuncAttributeMaxDynamicSharedMemorySize,
                         (int)FC_SMEM);

    int nblk = (n + 63) / 64;
    k_fc<<<nblk, 256, FC_SMEM>>>(x, W, b, (const int*)nid, n);
    k_route<<<(n + 1) / 2, 256>>>(nid, out, n);
}

// round 17
// speedup vs baseline: 1.1580x; 1.0399x over previous
#include <cuda_runtime.h>
#include <cstdint>

// ---------------------------------------------------------------------------
// Routing_2259152797848: capsule routing
// R17 = locked k_route (R13, 209.5us) + k_fc rewritten on tensor cores:
//       3xTF32 mma.sync.m16n8k8 (fp32-class accuracy), 64 rows x 128 cols
//       per 256-thread block, warp tile M16 x N64.
// ---------------------------------------------------------------------------

#define MAXN 50016
#define D    128
#define CH   8
#define KD   16
#define M    32

__device__ float g_z[(size_t)(MAXN + 1) * D];
__device__ int   g_is64;

__device__ __forceinline__ uint32_t tf32_of(float f) {
    uint32_t r; asm("cvt.rna.tf32.f32 %0, %1;" : "=r"(r) : "f"(f)); return r;
}

#define MMA_TF32(acc, A0, A1, A2, A3, B0, B1)                                  \
    asm("mma.sync.aligned.m16n8k8.row.col.f32.tf32.tf32.f32 "                  \
        "{%0,%1,%2,%3},{%4,%5,%6,%7},{%8,%9},{%0,%1,%2,%3};"                   \
        : "+f"((acc)[0]), "+f"((acc)[1]), "+f"((acc)[2]), "+f"((acc)[3])       \
        : "r"(A0), "r"(A1), "r"(A2), "r"(A3), "r"(B0), "r"(B1))

// --- FC + relu + per-capsule normalize: tensor-core 3xTF32 ---------------------
// Block: 256 threads = 8 warps, 64 rows x 128 cols.
// Warp w: M-tile m0 = (w&3)*16, N-half nbase = (w>>2)*64 (8 n8-tiles).
// SMEM rows padded to 132 floats: A-frag banks (4r+k), B-frag banks (4c+k)
// both bijective mod 32 -> conflict-free.
__global__ void k_fc(const float* __restrict__ x, const float* __restrict__ W,
                     const float* __restrict__ b, const int* __restrict__ nidw,
                     int n) {
    extern __shared__ float smem[];
    float* w_s = smem;              // [128][132]  w_s[j*132+k] = W[j][k]
    float* x_s = smem + 128 * 132;  // [64][132]

    const int t = threadIdx.x;
    const int r0 = blockIdx.x * 64;

    // folded init (block 0 only): zero pad row + id-width sniff
    if (blockIdx.x == 0) {
        if (t < 128) g_z[(size_t)n * D + t] = 0.0f;
        else if (t < 160) {
            int lane = t - 128;
            int any = 0;
            #pragma unroll
            for (int i = 0; i < 4; i++) any |= nidw[2 * (lane * 4 + i) + 1];
            unsigned msk = __ballot_sync(0xffffffffu, any != 0);
            if (lane == 0) g_is64 = (msk == 0) ? 1 : 0;
        }
    }

    // load W (4096 float4) into 33-float4 padded rows
    const float4* W4 = (const float4*)W;
    float4* ws4 = (float4*)w_s;
    #pragma unroll
    for (int i = 0; i < 16; i++) {
        int idx4 = t + 256 * i;
        int j = idx4 >> 5, kk = idx4 & 31;
        ws4[j * 33 + kk] = W4[idx4];
    }
    // load x tile (2048 float4), zero-fill past n, 33-float4 padded rows
    const float4* X4 = (const float4*)x;
    float4* xs4 = (float4*)x_s;
    #pragma unroll
    for (int i = 0; i < 8; i++) {
        int idx4 = t + 256 * i;
        int r = idx4 >> 5, kk = idx4 & 31;
        float4 v = make_float4(0.f, 0.f, 0.f, 0.f);
        if (r0 + r < n) v = X4[(size_t)(r0 + r) * 32 + kk];
        xs4[r * 33 + kk] = v;
    }
    __syncthreads();

    const int lane = t & 31;
    const int wid  = t >> 5;
    const int m0    = (wid & 3) * 16;   // warp M-tile
    const int nbase = (wid >> 2) * 64;  // warp N-half
    const int qr = lane >> 2;           // fragment row group (0..7)
    const int qc = lane & 3;            // fragment col group (0..3)

    float acc[8][4];
    #pragma unroll
    for (int nt = 0; nt < 8; nt++)
        #pragma unroll
        for (int c = 0; c < 4; c++) acc[nt][c] = 0.f;

    #pragma unroll 4
    for (int ks = 0; ks < 16; ks++) {
        // A fragments (x tile): row = m0+qr(+8), col = 8ks+qc(+4)
        int ka = ks * 8 + qc;
        float a0 = x_s[(m0 + qr)     * 132 + ka];
        float a1 = x_s[(m0 + qr + 8) * 132 + ka];
        float a2 = x_s[(m0 + qr)     * 132 + ka + 4];
        float a3 = x_s[(m0 + qr + 8) * 132 + ka + 4];
        uint32_t ah0 = tf32_of(a0), ah1 = tf32_of(a1);
        uint32_t ah2 = tf32_of(a2), ah3 = tf32_of(a3);
        uint32_t al0 = tf32_of(a0 - __uint_as_float(ah0));
        uint32_t al1 = tf32_of(a1 - __uint_as_float(ah1));
        uint32_t al2 = tf32_of(a2 - __uint_as_float(ah2));
        uint32_t al3 = tf32_of(a3 - __uint_as_float(ah3));

        #pragma unroll
        for (int nt = 0; nt < 8; nt++) {
            // B fragments: B[k][col] = W[col][k]; k = 8ks+qc(+4), col = nbase+8nt+qr
            int col = nbase + nt * 8 + qr;
            float f0 = w_s[col * 132 + ks * 8 + qc];
            float f1 = w_s[col * 132 + ks * 8 + qc + 4];
            uint32_t bh0 = tf32_of(f0), bh1 = tf32_of(f1);
            uint32_t bl0 = tf32_of(f0 - __uint_as_float(bh0));
            uint32_t bl1 = tf32_of(f1 - __uint_as_float(bh1));
            // 3xTF32: Ah*Bh + Ah*Bl + Al*Bh
            MMA_TF32(acc[nt], ah0, ah1, ah2, ah3, bh0, bh1);
            MMA_TF32(acc[nt], ah0, ah1, ah2, ah3, bl0, bl1);
            MMA_TF32(acc[nt], al0, al1, al2, al3, bh0, bh1);
        }
    }

    // epilogue: relu + bias, per-capsule (16-col) L2 normalize, store.
    // D frag: c0/c1 -> row m0+qr,   cols 8nt+2qc, +1
    //         c2/c3 -> row m0+qr+8, same cols
    // Quad (lanes 4qr..4qr+3) covers a full 16-col capsule via nt pair (2j,2j+1).
    const int row0 = r0 + m0 + qr;
    const int row1 = row0 + 8;
    #pragma unroll
    for (int j = 0; j < 4; j++) {
        int ntA = 2 * j, ntB = 2 * j + 1;
        float2 bvA = *(const float2*)&b[nbase + ntA * 8 + 2 * qc];
        float2 bvB = *(const float2*)&b[nbase + ntB * 8 + 2 * qc];
        #pragma unroll
        for (int h = 0; h < 2; h++) {
            float vA0 = fmaxf(acc[ntA][2 * h + 0] + bvA.x, 0.f);
            float vA1 = fmaxf(acc[ntA][2 * h + 1] + bvA.y, 0.f);
            float vB0 = fmaxf(acc[ntB][2 * h + 0] + bvB.x, 0.f);
            float vB1 = fmaxf(acc[ntB][2 * h + 1] + bvB.y, 0.f);
            float s = vA0 * vA0 + vA1 * vA1 + vB0 * vB0 + vB1 * vB1;
            s += __shfl_xor_sync(0xffffffffu, s, 1);
            s += __shfl_xor_sync(0xffffffffu, s, 2);
            float inv = rsqrtf(fmaxf(s, 1e-24f));
            int row = h ? row1 : row0;
            if (row < n) {
                float* dst = &g_z[(size_t)row * D + nbase + ntA * 8 + 2 * qc];
                *(float2*)dst       = make_float2(vA0 * inv, vA1 * inv);
                *(float2*)(dst + 8) = make_float2(vB0 * inv, vB1 * inv);
            }
        }
    }
}

// --- routing: 256 threads = 2 independent nodes (LOCKED, R13 verbatim) ---------
__global__ __launch_bounds__(256) void k_route(const void* __restrict__ nid_raw,
                                               float* __restrict__ out, int n) {
    __shared__ float d_s[2][M * 9];          // d_s[grp][m*9+c]
    __shared__ __align__(16) float ps[2][CH * 36];  // ps[grp][c*36+m]
    __shared__ int ids[2][M];

    const int t   = threadIdx.x;
    const int grp = t >> 7;                  // node group 0/1
    const int tl  = t & 127;
    const int bid = 1 + grp;                 // named barrier id (warp-uniform)
    const int node = blockIdx.x * 2 + grp;
    if (node >= n) return;                   // whole 128-group exits together
    const int is64 = g_is64;

    if (tl < M) {
        long long id;
        if (is64) id = ((const long long*)nid_raw)[(size_t)node * M + tl];
        else      id = (long long)((const int*)nid_raw)[(size_t)node * M + tl];
        ids[grp][tl] = (int)id;
    }
    const float xc = g_z[(size_t)node * D + tl];
    asm volatile("bar.sync %0, %1;" :: "r"(bid), "r"(128) : "memory");

    // coalesced gather: one (c,k) column of all 32 neighbor rows
    float nbr[M];
    #pragma unroll
    for (int m = 0; m < M; m++)
        nbr[m] = g_z[(size_t)ids[grp][m] * D + tl];

    const int cB = tl >> 4;          // channel (tree / phase B)
    const int g  = tl & 15;          // lane within 16-lane channel group
    const int m0 = tl >> 3;          // softmax identity
    const int cA = tl & 7;
    const int mbase = ((g & 1) << 4) | ((g & 2) << 2) | (g & 4) | ((g >> 3) << 1);

    float u_val = xc;
    float acc;

    for (int it = 0; it < 3; it++) {
        // ---- tree: d[m] = sum_k u[c,k]*nb[m,c,k], split over 16 lanes ----
        float s1[16];
        #pragma unroll
        for (int i = 0; i < 16; i++) {
            float lo = u_val * nbr[i];
            float hi = u_val * nbr[i + 16];
            float keep = (g & 1) ? hi : lo;
            float send = (g & 1) ? lo : hi;
            s1[i] = keep + __shfl_xor_sync(0xffffffffu, send, 1);
        }
        float s2[8];
        #pragma unroll
        for (int i = 0; i < 8; i++) {
            float keep = (g & 2) ? s1[i + 8] : s1[i];
            float send = (g & 2) ? s1[i] : s1[i + 8];
            s2[i] = keep + __shfl_xor_sync(0xffffffffu, send, 2);
        }
        float s3[4];
        #pragma unroll
        for (int i = 0; i < 4; i++) {
            float keep = (g & 4) ? s2[i + 4] : s2[i];
            float send = (g & 4) ? s2[i] : s2[i + 4];
            s3[i] = keep + __shfl_xor_sync(0xffffffffu, send, 4);
        }
        float s4[2];
        #pragma unroll
        for (int i = 0; i < 2; i++) {
            float keep = (g & 8) ? s3[i + 2] : s3[i];
            float send = (g & 8) ? s3[i] : s3[i + 2];
            s4[i] = keep + __shfl_xor_sync(0xffffffffu, send, 8);
        }
        // |d| <= 1 (unit capsules): exp safe without max-subtraction
        d_s[grp][(mbase + 0) * 9 + cB] = __expf(s4[0]);
        d_s[grp][(mbase + 1) * 9 + cB] = __expf(s4[1]);
        asm volatile("bar.sync %0, %1;" :: "r"(bid), "r"(128) : "memory");

        // ---- softmax over c (8 adjacent lanes), thread = (m0, cA) ----
        float e0 = d_s[grp][m0 * 9 + cA];
        float e1 = d_s[grp][(m0 + 16) * 9 + cA];
        float sm0 = e0, sm1 = e1;
        sm0 += __shfl_xor_sync(0xffffffffu, sm0, 1);
        sm1 += __shfl_xor_sync(0xffffffffu, sm1, 1);
        sm0 += __shfl_xor_sync(0xffffffffu, sm0, 2);
        sm1 += __shfl_xor_sync(0xffffffffu, sm1, 2);
        sm0 += __shfl_xor_sync(0xffffffffu, sm0, 4);
        sm1 += __shfl_xor_sync(0xffffffffu, sm1, 4);
        ps[grp][cA * 36 + m0]      = __fdividef(e0, sm0);
        ps[grp][cA * 36 + m0 + 16] = __fdividef(e1, sm1);
        asm volatile("bar.sync %0, %1;" :: "r"(bid), "r"(128) : "memory");

        // ---- phase B: u[c,k] = x_caps + sum_m p[m,c]*nb[m,c,k] ----
        acc = xc;
        #pragma unroll
        for (int j = 0; j < 8; j++) {
            float4 p = *(const float4*)&ps[grp][cB * 36 + 4 * j];
            acc = fmaf(p.x, nbr[4 * j + 0], acc);
            acc = fmaf(p.y, nbr[4 * j + 1], acc);
            acc = fmaf(p.z, nbr[4 * j + 2], acc);
            acc = fmaf(p.w, nbr[4 * j + 3], acc);
        }

        if (it < 2) {
            float sq = acc * acc;
            sq += __shfl_xor_sync(0xffffffffu, sq, 1);
            sq += __shfl_xor_sync(0xffffffffu, sq, 2);
            sq += __shfl_xor_sync(0xffffffffu, sq, 4);
            sq += __shfl_xor_sync(0xffffffffu, sq, 8);
            u_val = acc * rsqrtf(fmaxf(sq, 1e-24f));
        } else {
            out[(size_t)node * D + tl] = acc;
        }
    }
}

// ---------------------------------------------------------------------------
extern "C" void kernel_launch(void* const* d_in, const int* in_sizes, int n_in,
                              void* d_out, int out_size) {
    const float* x = (const float*)d_in[0];
    const float* W = (const float*)d_in[1];
    const float* b = (const float*)d_in[2];
    const void*  nid = d_in[3];
    float* out = (float*)d_out;

    int n = in_sizes[0] / D;

    // W smem [128][132] + x smem [64][132] = (16896 + 8448) * 4 = 101,376 bytes
    static const size_t FC_SMEM = (size_t)(128 * 132 + 64 * 132) * sizeof(float);
    cudaFuncSetAttribute(k_fc, cudaFuncAttributeMaxDynamicSharedMemorySize,
                         (int)FC_SMEM);

    int nblk = (n + 63) / 64;
    k_fc<<<nblk, 256, FC_SMEM>>>(x, W, b, (const int*)nid, n);
    k_route<<<(n + 1) / 2, 256>>>(nid, out, n);
}